// round 1
// baseline (speedup 1.0000x reference)
#include <cuda_runtime.h>
#include <cuda_bf16.h>

typedef unsigned long long u64;

// ---------------- scratch (device globals; no allocation allowed) ----------
__device__ float g_h1[2 * 512];
__device__ float g_z[2 * 64];
__device__ float g_d1[2 * 64 * 128];
__device__ float g_d2[2 * 64 * 512];
__device__ float g_Y[2 * 65536 * 3];
__device__ float g_lossA;
__device__ unsigned g_aminU[2 * 65536];   // per-Y min (sortable uint)
__device__ unsigned g_bminU[2 * 1024];    // per-S min (sortable uint)

// ---------------- f32x2 helpers -------------------------------------------
__device__ __forceinline__ u64 pk2(float a, float b) {
    u64 r; asm("mov.b64 %0, {%1,%2};" : "=l"(r) : "f"(a), "f"(b)); return r;
}
__device__ __forceinline__ float2 upk(u64 v) {
    float2 r; asm("mov.b64 {%0,%1}, %2;" : "=f"(r.x), "=f"(r.y) : "l"(v)); return r;
}
__device__ __forceinline__ u64 fma2_(u64 a, u64 b, u64 c) {
    u64 d; asm("fma.rn.f32x2 %0, %1, %2, %3;" : "=l"(d) : "l"(a), "l"(b), "l"(c)); return d;
}
__device__ __forceinline__ u64 add2_(u64 a, u64 b) {
    u64 d; asm("add.rn.f32x2 %0, %1, %2;" : "=l"(d) : "l"(a), "l"(b)); return d;
}

// sortable-uint encoding of float (ascending order preserved)
__device__ __forceinline__ unsigned f2key(float f) {
    unsigned b = __float_as_uint(f);
    return b ^ ((unsigned)((int)b >> 31) | 0x80000000u);
}
__device__ __forceinline__ float key2f(unsigned k) {
    unsigned b = (k & 0x80000000u) ? (k ^ 0x80000000u) : ~k;
    return __uint_as_float(b);
}

// ---------------- init ----------------------------------------------------
__global__ void k_init() {
    int t = blockIdx.x * blockDim.x + threadIdx.x;
    if (t < 2 * 65536) g_aminU[t] = 0xFFFFFFFFu;
    if (t < 2048)      g_bminU[t] = 0xFFFFFFFFu;
    if (t == 0)        g_lossA = 0.0f;
}

// ---------------- encoder layer 1: [2,3072] x [3072,512] -------------------
// grid (16, 2), 256 threads: 32 cols x 8 k-slices per block
__global__ void k_enc1(const float* __restrict__ x, const float* __restrict__ We1,
                       const float* __restrict__ be1) {
    __shared__ float xs[3072];
    __shared__ float red[256];
    int b    = blockIdx.y;
    int lane = threadIdx.x & 31;
    int ks   = threadIdx.x >> 5;
    int col  = blockIdx.x * 32 + lane;
    for (int i = threadIdx.x; i < 3072; i += 256) xs[i] = x[b * 3072 + i];
    __syncthreads();
    float acc = 0.0f;
    int k0 = ks * 384;
#pragma unroll 4
    for (int k = k0; k < k0 + 384; ++k) acc = fmaf(xs[k], We1[k * 512 + col], acc);
    red[threadIdx.x] = acc;
    __syncthreads();
    if (threadIdx.x < 32) {
        float s = 0.0f;
#pragma unroll
        for (int r = 0; r < 8; ++r) s += red[threadIdx.x + r * 32];
        s += be1[col];
        g_h1[b * 512 + col] = fmaxf(s, 0.0f);
    }
}

// ---------------- encoder layers 2+3 --------------------------------------
// grid (2), 128 threads
__global__ void k_enc2(const float* __restrict__ We2, const float* __restrict__ be2,
                       const float* __restrict__ We3, const float* __restrict__ be3) {
    __shared__ float h1s[512];
    __shared__ float h2s[128];
    int b = blockIdx.x;
    int t = threadIdx.x;
    for (int i = t; i < 512; i += 128) h1s[i] = g_h1[b * 512 + i];
    __syncthreads();
    float acc = be2[t];
#pragma unroll 4
    for (int k = 0; k < 512; ++k) acc = fmaf(h1s[k], We2[k * 128 + t], acc);
    h2s[t] = fmaxf(acc, 0.0f);
    __syncthreads();
    if (t < 64) {
        float a2 = be3[t];
#pragma unroll 4
        for (int k = 0; k < 128; ++k) a2 = fmaf(h2s[k], We3[k * 64 + t], a2);
        g_z[b * 64 + t] = fmaxf(a2, 0.0f);
    }
}

// ---------------- decoder layer 1: [128 rows, 67] x [67, 128] --------------
// grid (128), 128 threads
__global__ void k_dec1(const float* __restrict__ grid_pts, const float* __restrict__ Wd1,
                       const float* __restrict__ bd1) {
    __shared__ float zi[67];
    int row = blockIdx.x;          // b*64 + g
    int b = row >> 6, g = row & 63;
    int t = threadIdx.x;
    if (t < 64)      zi[t] = g_z[b * 64 + t];
    else if (t < 67) zi[t] = grid_pts[g * 3 + (t - 64)];
    __syncthreads();
    float acc = bd1[t];
#pragma unroll
    for (int k = 0; k < 67; ++k) acc = fmaf(zi[k], Wd1[k * 128 + t], acc);
    g_d1[row * 128 + t] = fmaxf(acc, 0.0f);
}

// ---------------- decoder layer 2: [128,128] x [128,512] -------------------
// grid (32), 512 threads: 4 rows per block
__global__ void k_dec2(const float* __restrict__ Wd2, const float* __restrict__ bd2) {
    __shared__ float a[4 * 128];
    int r0 = blockIdx.x * 4;
    int t = threadIdx.x;
    a[t] = g_d1[r0 * 128 + t];
    __syncthreads();
    float a0 = 0.f, a1 = 0.f, a2 = 0.f, a3 = 0.f;
#pragma unroll 4
    for (int k = 0; k < 128; ++k) {
        float w = Wd2[k * 512 + t];
        a0 = fmaf(a[k],       w, a0);
        a1 = fmaf(a[128 + k], w, a1);
        a2 = fmaf(a[256 + k], w, a2);
        a3 = fmaf(a[384 + k], w, a3);
    }
    float bb = bd2[t];
    g_d2[(r0 + 0) * 512 + t] = fmaxf(a0 + bb, 0.0f);
    g_d2[(r0 + 1) * 512 + t] = fmaxf(a1 + bb, 0.0f);
    g_d2[(r0 + 2) * 512 + t] = fmaxf(a2 + bb, 0.0f);
    g_d2[(r0 + 3) * 512 + t] = fmaxf(a3 + bb, 0.0f);
}

// ---------------- decoder layer 3: [128,512] x [512,3072] + tanh -----------
// grid (24, 8), 128 threads: 128 cols x 16 rows per block; f32x2 FMA
__global__ void k_dec3(const float* __restrict__ Wd3, const float* __restrict__ bd3) {
    __shared__ __align__(16) float As[512 * 18];   // [k][r], pad 18 (LDS.64-aligned)
    int r0  = blockIdx.y * 16;
    int col = blockIdx.x * 128 + threadIdx.x;
    for (int idx = threadIdx.x; idx < 16 * 512; idx += 128) {
        int r = idx >> 9, k = idx & 511;
        As[k * 18 + r] = g_d2[(r0 + r) * 512 + k];
    }
    __syncthreads();
    u64 acc[8];
#pragma unroll
    for (int p = 0; p < 8; ++p) acc[p] = 0ull;
#pragma unroll 2
    for (int k = 0; k < 512; ++k) {
        float w = Wd3[k * 3072 + col];
        u64 w2 = pk2(w, w);
        const u64* ap = (const u64*)&As[k * 18];
#pragma unroll
        for (int p = 0; p < 8; ++p) acc[p] = fma2_(ap[p], w2, acc[p]);
    }
    float bb = bd3[col];
#pragma unroll
    for (int p = 0; p < 8; ++p) {
        float2 v = upk(acc[p]);
        g_Y[(r0 + 2 * p + 0) * 3072 + col] = tanhf(v.x + bb);
        g_Y[(r0 + 2 * p + 1) * 3072 + col] = tanhf(v.y + bb);
    }
}

// ---------------- symmetric chamfer ----------------------------------------
// v = 0.5|y|^2 + 0.5|s|^2 - y.s  =>  d2 = 2v (symmetric for both directions)
// grid (64, 2): bx = yt*4 + ms (16 Y-tiles of 4096, 4 m-slices of 256). 256 thr.
__global__ void __launch_bounds__(256) k_chamfer(const float* __restrict__ x) {
    __shared__ __align__(16) u64 sd[256 * 4];   // per-m: {-sx,-sx},{-sy,-sy},{-sz,-sz},{hs,hs}
    __shared__ unsigned sbmin[256];
    int b   = blockIdx.y;
    int yt  = blockIdx.x >> 2;
    int ms  = blockIdx.x & 3;
    int t   = threadIdx.x;
    int wid = t >> 5, lane = t & 31;
    int m0  = ms * 256;

    {   // load S slice (256 points), precompute packed negated coords + half-norm
        int m = m0 + t;
        float sx = x[(b * 1024 + m) * 3 + 0];
        float sy = x[(b * 1024 + m) * 3 + 1];
        float sz = x[(b * 1024 + m) * 3 + 2];
        float hs = 0.5f * (sx * sx + sy * sy + sz * sz);
        sd[t * 4 + 0] = pk2(-sx, -sx);
        sd[t * 4 + 1] = pk2(-sy, -sy);
        sd[t * 4 + 2] = pk2(-sz, -sz);
        sd[t * 4 + 3] = pk2(hs, hs);
        sbmin[t] = 0xFFFFFFFFu;
    }

    // load 16 Y points per thread, pack into f32x2 pairs
    int nbase = b * 65536 + yt * 4096;
    float yv[16][3], hyv[16];
#pragma unroll
    for (int j = 0; j < 16; ++j) {
        int n = nbase + j * 256 + t;
        float a0 = g_Y[n * 3 + 0], a1 = g_Y[n * 3 + 1], a2 = g_Y[n * 3 + 2];
        yv[j][0] = a0; yv[j][1] = a1; yv[j][2] = a2;
        hyv[j] = 0.5f * (a0 * a0 + a1 * a1 + a2 * a2);
    }
    u64 px[8], py[8], pz[8], ph[8];
#pragma unroll
    for (int p = 0; p < 8; ++p) {
        px[p] = pk2(yv[2 * p][0], yv[2 * p + 1][0]);
        py[p] = pk2(yv[2 * p][1], yv[2 * p + 1][1]);
        pz[p] = pk2(yv[2 * p][2], yv[2 * p + 1][2]);
        ph[p] = pk2(hyv[2 * p], hyv[2 * p + 1]);
    }
    float amin[16];
#pragma unroll
    for (int j = 0; j < 16; ++j) amin[j] = 3.4e38f;
    __syncthreads();

    int moff = (wid * 32) & 255;   // stagger warps across m to decorrelate atomics
    for (int mi = 0; mi < 256; ++mi) {
        int mm = (mi + moff) & 255;
        ulonglong2 q0 = *(const ulonglong2*)&sd[mm * 4];
        ulonglong2 q1 = *(const ulonglong2*)&sd[mm * 4 + 2];
        u64 nx = q0.x, ny = q0.y, nz = q1.x, hs2 = q1.y;
        float bcur = 3.4e38f;
#pragma unroll
        for (int p = 0; p < 8; ++p) {
            u64 v2 = fma2_(px[p], nx, fma2_(py[p], ny, fma2_(pz[p], nz, add2_(ph[p], hs2))));
            float2 v = upk(v2);
            amin[2 * p + 0] = fminf(amin[2 * p + 0], v.x);
            amin[2 * p + 1] = fminf(amin[2 * p + 1], v.y);
            bcur = fminf(bcur, fminf(v.x, v.y));
        }
#pragma unroll
        for (int s = 16; s > 0; s >>= 1)
            bcur = fminf(bcur, __shfl_xor_sync(0xFFFFFFFFu, bcur, s));
        if (lane == 0) atomicMin(&sbmin[mm], f2key(bcur));
    }
    __syncthreads();

    atomicMin(&g_bminU[b * 1024 + m0 + t], sbmin[t]);
#pragma unroll
    for (int j = 0; j < 16; ++j) {
        int n = nbase + j * 256 + t;
        atomicMin(&g_aminU[n], f2key(amin[j]));
    }
}

// ---------------- finals ----------------------------------------------------
__global__ void k_fina() {   // grid (64), 256 thr: sum per-Y mins
    __shared__ float red[256];
    int base = blockIdx.x * 2048;
    float s = 0.0f;
    for (int i = threadIdx.x; i < 2048; i += 256) s += key2f(g_aminU[base + i]);
    red[threadIdx.x] = s;
    __syncthreads();
    for (int st = 128; st > 0; st >>= 1) {
        if (threadIdx.x < st) red[threadIdx.x] += red[threadIdx.x + st];
        __syncthreads();
    }
    if (threadIdx.x == 0) atomicAdd(&g_lossA, red[0]);
}

__global__ void k_finb(float* __restrict__ out) {   // 1 block, 256 thr
    __shared__ float red[256];
    float s = 0.0f;
    for (int i = threadIdx.x; i < 2048; i += 256) s += key2f(g_bminU[i]);
    red[threadIdx.x] = s;
    __syncthreads();
    for (int st = 128; st > 0; st >>= 1) {
        if (threadIdx.x < st) red[threadIdx.x] += red[threadIdx.x + st];
        __syncthreads();
    }
    if (threadIdx.x == 0) out[0] = 2.0f * (red[0] + g_lossA);
}

// ---------------- launch ----------------------------------------------------
extern "C" void kernel_launch(void* const* d_in, const int* in_sizes, int n_in,
                              void* d_out, int out_size) {
    const float* x    = (const float*)d_in[0];
    const float* grid = (const float*)d_in[1];
    const float* We1  = (const float*)d_in[2];
    const float* be1  = (const float*)d_in[3];
    const float* We2  = (const float*)d_in[4];
    const float* be2  = (const float*)d_in[5];
    const float* We3  = (const float*)d_in[6];
    const float* be3  = (const float*)d_in[7];
    const float* Wd1  = (const float*)d_in[8];
    const float* bd1  = (const float*)d_in[9];
    const float* Wd2  = (const float*)d_in[10];
    const float* bd2  = (const float*)d_in[11];
    const float* Wd3  = (const float*)d_in[12];
    const float* bd3  = (const float*)d_in[13];
    float* out = (float*)d_out;

    k_init<<<256, 512>>>();
    k_enc1<<<dim3(16, 2), 256>>>(x, We1, be1);
    k_enc2<<<2, 128>>>(We2, be2, We3, be3);
    k_dec1<<<128, 128>>>(grid, Wd1, bd1);
    k_dec2<<<32, 512>>>(Wd2, bd2);
    k_dec3<<<dim3(24, 8), 128>>>(Wd3, bd3);
    k_chamfer<<<dim3(64, 2), 256>>>(x);
    k_fina<<<64, 256>>>();
    k_finb<<<1, 256>>>(out);
}

// round 2
// speedup vs baseline: 1.4895x; 1.4895x over previous
#include <cuda_runtime.h>
#include <cuda_bf16.h>

typedef unsigned long long u64;

// ---------------- scratch (device globals; no allocation allowed) ----------
__device__ float g_p1[8 * 2 * 512];       // enc1 k-partials
__device__ float g_z[2 * 64];
__device__ float g_d2[2 * 64 * 512];
__device__ float g_Y[2 * 65536 * 3];
__device__ float g_lossA;
__device__ unsigned g_aminU[2 * 65536];   // per-Y min (sortable uint)
__device__ unsigned g_bminU[2 * 1024];    // per-S min (sortable uint)

// ---------------- f32x2 helpers -------------------------------------------
__device__ __forceinline__ u64 pk2(float a, float b) {
    u64 r; asm("mov.b64 %0, {%1,%2};" : "=l"(r) : "f"(a), "f"(b)); return r;
}
__device__ __forceinline__ float2 upk(u64 v) {
    float2 r; asm("mov.b64 {%0,%1}, %2;" : "=f"(r.x), "=f"(r.y) : "l"(v)); return r;
}
__device__ __forceinline__ u64 fma2_(u64 a, u64 b, u64 c) {
    u64 d; asm("fma.rn.f32x2 %0, %1, %2, %3;" : "=l"(d) : "l"(a), "l"(b), "l"(c)); return d;
}
__device__ __forceinline__ u64 add2_(u64 a, u64 b) {
    u64 d; asm("add.rn.f32x2 %0, %1, %2;" : "=l"(d) : "l"(a), "l"(b)); return d;
}
__device__ __forceinline__ unsigned f2key(float f) {
    unsigned b = __float_as_uint(f);
    return b ^ ((unsigned)((int)b >> 31) | 0x80000000u);
}
__device__ __forceinline__ float key2f(unsigned k) {
    unsigned b = (k & 0x80000000u) ? (k ^ 0x80000000u) : ~k;
    return __uint_as_float(b);
}

// ---------------- init ----------------------------------------------------
__global__ void k_init() {
    int t = blockIdx.x * blockDim.x + threadIdx.x;
    if (t < 2 * 65536) g_aminU[t] = 0xFFFFFFFFu;
    if (t < 2048)      g_bminU[t] = 0xFFFFFFFFu;
    if (t == 0)        g_lossA = 0.0f;
}

// ---------------- encoder layer 1 (k-split partials) -----------------------
// grid (16 colgroups, 8 kslices), 256 thr: warp w -> 48 k's, lane -> col
__global__ void k_enc1(const float* __restrict__ x, const float* __restrict__ We1) {
    __shared__ float xs[2][384];
    __shared__ float red[2][256];
    int t = threadIdx.x, w = t >> 5, l = t & 31;
    int bx = blockIdx.x, by = blockIdx.y;
    int col = bx * 32 + l;
    for (int i = t; i < 768; i += 256) {
        int b = i >> 9 ? 1 : (i >= 384);   // i<384 -> b0, else b1
        int kk = (i < 384) ? i : i - 384;
        xs[(i < 384) ? 0 : 1][kk] = x[((i < 384) ? 0 : 1) * 3072 + by * 384 + kk];
        (void)b;
    }
    __syncthreads();
    float a0 = 0.0f, a1 = 0.0f;
    int k0 = by * 384 + w * 48;
    int kl0 = w * 48;
#pragma unroll 16
    for (int j = 0; j < 48; ++j) {
        float wt = We1[(k0 + j) * 512 + col];
        a0 = fmaf(xs[0][kl0 + j], wt, a0);
        a1 = fmaf(xs[1][kl0 + j], wt, a1);
    }
    red[0][t] = a0;
    red[1][t] = a1;
    __syncthreads();
    if (t < 64) {
        int b = t >> 5, ll = t & 31;
        float s = 0.0f;
#pragma unroll
        for (int r = 0; r < 8; ++r) s += red[b][r * 32 + ll];
        g_p1[(by * 2 + b) * 512 + bx * 32 + ll] = s;
    }
}

// ---------------- encoder: combine + layers 2,3 ----------------------------
// grid (2), 512 threads
__global__ void k_enc2(const float* __restrict__ be1,
                       const float* __restrict__ We2, const float* __restrict__ be2,
                       const float* __restrict__ We3, const float* __restrict__ be3) {
    __shared__ float h1s[512];
    __shared__ float hp[4][128];
    __shared__ float h2s[128];
    __shared__ float zp[8][64];
    int b = blockIdx.x, t = threadIdx.x;
    {   // combine enc1 partials + bias + relu
        float s = be1[t];
#pragma unroll
        for (int sl = 0; sl < 8; ++sl) s += g_p1[(sl * 2 + b) * 512 + t];
        h1s[t] = fmaxf(s, 0.0f);
    }
    __syncthreads();
    {   // h2: 128 cols x 4 k-slices of 128
        int ks = t >> 7, col = t & 127;
        float acc = 0.0f;
        int k0 = ks * 128;
#pragma unroll 16
        for (int j = 0; j < 128; ++j) acc = fmaf(h1s[k0 + j], We2[(k0 + j) * 128 + col], acc);
        hp[ks][col] = acc;
    }
    __syncthreads();
    if (t < 128) {
        float s = hp[0][t] + hp[1][t] + hp[2][t] + hp[3][t] + be2[t];
        h2s[t] = fmaxf(s, 0.0f);
    }
    __syncthreads();
    {   // z: 64 cols x 8 k-slices of 16
        int ks = t >> 6, col = t & 63;
        float acc = 0.0f;
        int k0 = ks * 16;
#pragma unroll
        for (int j = 0; j < 16; ++j) acc = fmaf(h2s[k0 + j], We3[(k0 + j) * 64 + col], acc);
        zp[ks][col] = acc;
    }
    __syncthreads();
    if (t < 64) {
        float s = be3[t];
#pragma unroll
        for (int sl = 0; sl < 8; ++sl) s += zp[sl][t];
        g_z[b * 64 + t] = fmaxf(s, 0.0f);
    }
}

// ---------------- decoder layers 1+2 fused ---------------------------------
// grid (64): 2 rows per block, 512 threads (= 512 dec2 cols)
__global__ void k_dec12(const float* __restrict__ grid_pts,
                        const float* __restrict__ Wd1, const float* __restrict__ bd1,
                        const float* __restrict__ Wd2, const float* __restrict__ bd2) {
    __shared__ float zi[2][67];
    __shared__ float d1s[2][128];
    __shared__ __align__(8) u64 d1p[128];
    int r0 = blockIdx.x * 2;           // rows r0, r0+1 (same batch: 2 | 64)
    int b = r0 >> 6;
    int t = threadIdx.x;
    if (t < 134) {
        int rw = (t >= 67), i = t - rw * 67;
        int g = (r0 + rw) & 63;
        zi[rw][i] = (i < 64) ? g_z[b * 64 + i] : grid_pts[g * 3 + (i - 64)];
    }
    __syncthreads();
    if (t < 256) {
        int rw = t >> 7, col = t & 127;
        float acc = bd1[col];
#pragma unroll
        for (int k = 0; k < 67; ++k) acc = fmaf(zi[rw][k], Wd1[k * 128 + col], acc);
        d1s[rw][col] = fmaxf(acc, 0.0f);
    }
    __syncthreads();
    if (t < 128) d1p[t] = pk2(d1s[0][t], d1s[1][t]);
    __syncthreads();
    u64 acc = 0ull;
#pragma unroll 16
    for (int k = 0; k < 128; ++k) {
        float wt = Wd2[k * 512 + t];
        acc = fma2_(d1p[k], pk2(wt, wt), acc);
    }
    float bb = bd2[t];
    float2 v = upk(acc);
    g_d2[(r0 + 0) * 512 + t] = fmaxf(v.x + bb, 0.0f);
    g_d2[(r0 + 1) * 512 + t] = fmaxf(v.y + bb, 0.0f);
}

// ---------------- decoder layer 3: [128,512] x [512,3072] + tanh -----------
// grid (24, 8), 128 threads: 128 cols x 16 rows; As padded to 20 (16B-aligned)
__global__ void k_dec3(const float* __restrict__ Wd3, const float* __restrict__ bd3) {
    __shared__ __align__(16) float As[512 * 20];   // [k][r], 80B rows -> LDS.128 ok
    int r0  = blockIdx.y * 16;
    int col = blockIdx.x * 128 + threadIdx.x;
    for (int idx = threadIdx.x; idx < 16 * 512; idx += 128) {
        int r = idx >> 9, k = idx & 511;
        As[k * 20 + r] = g_d2[(r0 + r) * 512 + k];
    }
    __syncthreads();
    u64 acc[8];
#pragma unroll
    for (int p = 0; p < 8; ++p) acc[p] = 0ull;
#pragma unroll 4
    for (int k = 0; k < 512; ++k) {
        float w = Wd3[k * 3072 + col];
        u64 w2 = pk2(w, w);
        const ulonglong2* ap = (const ulonglong2*)&As[k * 20];
        ulonglong2 q0 = ap[0], q1 = ap[1];
        acc[0] = fma2_(q0.x, w2, acc[0]);
        acc[1] = fma2_(q0.y, w2, acc[1]);
        acc[2] = fma2_(q1.x, w2, acc[2]);
        acc[3] = fma2_(q1.y, w2, acc[3]);
        ulonglong2 q2 = ap[2], q3 = ap[3];
        acc[4] = fma2_(q2.x, w2, acc[4]);
        acc[5] = fma2_(q2.y, w2, acc[5]);
        acc[6] = fma2_(q3.x, w2, acc[6]);
        acc[7] = fma2_(q3.y, w2, acc[7]);
    }
    float bb = bd3[col];
#pragma unroll
    for (int p = 0; p < 8; ++p) {
        float2 v = upk(acc[p]);
        g_Y[(r0 + 2 * p + 0) * 3072 + col] = tanhf(v.x + bb);
        g_Y[(r0 + 2 * p + 1) * 3072 + col] = tanhf(v.y + bb);
    }
}

// ---------------- symmetric chamfer ----------------------------------------
// v = 0.5|y|^2 + 0.5|s|^2 - y.s  =>  d2 = 2v (symmetric for both directions)
// grid (64, 2): bx = yt*4 + ms (16 Y-tiles of 4096, 4 m-slices of 256). 256 thr.
__global__ void __launch_bounds__(256) k_chamfer(const float* __restrict__ x) {
    __shared__ __align__(16) u64 sd[256 * 4];
    __shared__ unsigned sbmin[256];
    int b   = blockIdx.y;
    int yt  = blockIdx.x >> 2;
    int ms  = blockIdx.x & 3;
    int t   = threadIdx.x;
    int wid = t >> 5, lane = t & 31;
    int m0  = ms * 256;

    {   // load S slice (256 points): packed negated coords + half-norm
        int m = m0 + t;
        float sx = x[(b * 1024 + m) * 3 + 0];
        float sy = x[(b * 1024 + m) * 3 + 1];
        float sz = x[(b * 1024 + m) * 3 + 2];
        float hs = 0.5f * (sx * sx + sy * sy + sz * sz);
        sd[t * 4 + 0] = pk2(-sx, -sx);
        sd[t * 4 + 1] = pk2(-sy, -sy);
        sd[t * 4 + 2] = pk2(-sz, -sz);
        sd[t * 4 + 3] = pk2(hs, hs);
        sbmin[t] = 0xFFFFFFFFu;
    }

    int nbase = b * 65536 + yt * 4096;
    float yv[16][3], hyv[16];
#pragma unroll
    for (int j = 0; j < 16; ++j) {
        int n = nbase + j * 256 + t;
        float a0 = g_Y[n * 3 + 0], a1 = g_Y[n * 3 + 1], a2 = g_Y[n * 3 + 2];
        yv[j][0] = a0; yv[j][1] = a1; yv[j][2] = a2;
        hyv[j] = 0.5f * (a0 * a0 + a1 * a1 + a2 * a2);
    }
    u64 px[8], py[8], pz[8], ph[8];
#pragma unroll
    for (int p = 0; p < 8; ++p) {
        px[p] = pk2(yv[2 * p][0], yv[2 * p + 1][0]);
        py[p] = pk2(yv[2 * p][1], yv[2 * p + 1][1]);
        pz[p] = pk2(yv[2 * p][2], yv[2 * p + 1][2]);
        ph[p] = pk2(hyv[2 * p], hyv[2 * p + 1]);
    }
    float amin[16];
#pragma unroll
    for (int j = 0; j < 16; ++j) amin[j] = 3.4e38f;
    __syncthreads();

    int moff = (wid * 32) & 255;
    for (int mi = 0; mi < 256; ++mi) {
        int mm = (mi + moff) & 255;
        ulonglong2 q0 = *(const ulonglong2*)&sd[mm * 4];
        ulonglong2 q1 = *(const ulonglong2*)&sd[mm * 4 + 2];
        u64 nx = q0.x, ny = q0.y, nz = q1.x, hs2 = q1.y;
        float bcur = 3.4e38f;
#pragma unroll
        for (int p = 0; p < 8; ++p) {
            u64 v2 = fma2_(px[p], nx, fma2_(py[p], ny, fma2_(pz[p], nz, add2_(ph[p], hs2))));
            float2 v = upk(v2);
            amin[2 * p + 0] = fminf(amin[2 * p + 0], v.x);
            amin[2 * p + 1] = fminf(amin[2 * p + 1], v.y);
            bcur = fminf(bcur, fminf(v.x, v.y));
        }
#pragma unroll
        for (int s = 16; s > 0; s >>= 1)
            bcur = fminf(bcur, __shfl_xor_sync(0xFFFFFFFFu, bcur, s));
        if (lane == 0) atomicMin(&sbmin[mm], f2key(bcur));
    }
    __syncthreads();

    atomicMin(&g_bminU[b * 1024 + m0 + t], sbmin[t]);
#pragma unroll
    for (int j = 0; j < 16; ++j) {
        int n = nbase + j * 256 + t;
        atomicMin(&g_aminU[n], f2key(amin[j]));
    }
}

// ---------------- finals ----------------------------------------------------
__global__ void k_fina() {
    __shared__ float red[256];
    int base = blockIdx.x * 2048;
    float s = 0.0f;
    for (int i = threadIdx.x; i < 2048; i += 256) s += key2f(g_aminU[base + i]);
    red[threadIdx.x] = s;
    __syncthreads();
    for (int st = 128; st > 0; st >>= 1) {
        if (threadIdx.x < st) red[threadIdx.x] += red[threadIdx.x + st];
        __syncthreads();
    }
    if (threadIdx.x == 0) atomicAdd(&g_lossA, red[0]);
}

__global__ void k_finb(float* __restrict__ out) {
    __shared__ float red[256];
    float s = 0.0f;
    for (int i = threadIdx.x; i < 2048; i += 256) s += key2f(g_bminU[i]);
    red[threadIdx.x] = s;
    __syncthreads();
    for (int st = 128; st > 0; st >>= 1) {
        if (threadIdx.x < st) red[threadIdx.x] += red[threadIdx.x + st];
        __syncthreads();
    }
    if (threadIdx.x == 0) out[0] = 2.0f * (red[0] + g_lossA);
}

// ---------------- launch ----------------------------------------------------
extern "C" void kernel_launch(void* const* d_in, const int* in_sizes, int n_in,
                              void* d_out, int out_size) {
    const float* x    = (const float*)d_in[0];
    const float* grid = (const float*)d_in[1];
    const float* We1  = (const float*)d_in[2];
    const float* be1  = (const float*)d_in[3];
    const float* We2  = (const float*)d_in[4];
    const float* be2  = (const float*)d_in[5];
    const float* We3  = (const float*)d_in[6];
    const float* be3  = (const float*)d_in[7];
    const float* Wd1  = (const float*)d_in[8];
    const float* bd1  = (const float*)d_in[9];
    const float* Wd2  = (const float*)d_in[10];
    const float* bd2  = (const float*)d_in[11];
    const float* Wd3  = (const float*)d_in[12];
    const float* bd3  = (const float*)d_in[13];
    float* out = (float*)d_out;

    k_init<<<256, 512>>>();
    k_enc1<<<dim3(16, 8), 256>>>(x, We1);
    k_enc2<<<2, 512>>>(be1, We2, be2, We3, be3);
    k_dec12<<<64, 512>>>(grid, Wd1, bd1, Wd2, bd2);
    k_dec3<<<dim3(24, 8), 128>>>(Wd3, bd3);
    k_chamfer<<<dim3(64, 2), 256>>>(x);
    k_fina<<<64, 256>>>();
    k_finb<<<1, 256>>>(out);
}

// round 3
// speedup vs baseline: 1.7172x; 1.1529x over previous
#include <cuda_runtime.h>

typedef unsigned long long u64;

// ---------------- scratch (device globals; zero-initialized) ---------------
__device__ float g_p1[8 * 2 * 512];       // enc1 k-partials
__device__ float g_p2[4 * 2 * 128];       // enc2 h2 k-partials
__device__ float g_z[2 * 64];
__device__ float g_d2[2 * 64 * 512];
__device__ float g_Y[2 * 65536 * 3];
__device__ float g_lossA;
__device__ unsigned g_aminU[2 * 65536];
__device__ unsigned g_bminU[2 * 1024];
__device__ unsigned g_barcnt;             // global barrier counter (self-resetting)
__device__ unsigned g_done;               // drain counter for safe reset

// ---------------- f32x2 helpers -------------------------------------------
__device__ __forceinline__ u64 pk2(float a, float b) {
    u64 r; asm("mov.b64 %0, {%1,%2};" : "=l"(r) : "f"(a), "f"(b)); return r;
}
__device__ __forceinline__ float2 upk(u64 v) {
    float2 r; asm("mov.b64 {%0,%1}, %2;" : "=f"(r.x), "=f"(r.y) : "l"(v)); return r;
}
__device__ __forceinline__ u64 fma2_(u64 a, u64 b, u64 c) {
    u64 d; asm("fma.rn.f32x2 %0, %1, %2, %3;" : "=l"(d) : "l"(a), "l"(b), "l"(c)); return d;
}
__device__ __forceinline__ u64 add2_(u64 a, u64 b) {
    u64 d; asm("add.rn.f32x2 %0, %1, %2;" : "=l"(d) : "l"(a), "l"(b)); return d;
}
__device__ __forceinline__ unsigned f2key(float f) {
    unsigned b = __float_as_uint(f);
    return b ^ ((unsigned)((int)b >> 31) | 0x80000000u);
}
__device__ __forceinline__ float key2f(unsigned k) {
    unsigned b = (k & 0x80000000u) ? (k ^ 0x80000000u) : ~k;
    return __uint_as_float(b);
}

// ---------------- grid-wide spin barrier (all 128 blocks co-resident) ------
__device__ __forceinline__ void gbar(unsigned target) {
    __threadfence();
    __syncthreads();
    if (threadIdx.x == 0) {
        atomicAdd(&g_barcnt, 1u);
        while (*(volatile unsigned*)&g_barcnt < target) __nanosleep(32);
    }
    __syncthreads();
}

// ---------------- the megakernel -------------------------------------------
__global__ void __launch_bounds__(256, 1) k_mega(
    const float* __restrict__ x,   const float* __restrict__ grid_pts,
    const float* __restrict__ We1, const float* __restrict__ be1,
    const float* __restrict__ We2, const float* __restrict__ be2,
    const float* __restrict__ We3, const float* __restrict__ be3,
    const float* __restrict__ Wd1, const float* __restrict__ bd1,
    const float* __restrict__ Wd2, const float* __restrict__ bd2,
    const float* __restrict__ Wd3, const float* __restrict__ bd3,
    float* __restrict__ out)
{
    __shared__ __align__(16) unsigned char sraw[41024];
    const int t   = threadIdx.x;
    const int blk = blockIdx.x;

    // ===== P0: enc1 partials (all 128 blocks) + init mins/loss ==============
    {
        float* xs  = (float*)sraw;          // [2][384]
        float* red = xs + 768;              // [2][256]
        int bx = blk >> 3, by = blk & 7;    // 16 colgroups x 8 kslices
        int w = t >> 5, l = t & 31;
        int col = bx * 32 + l;
        for (int i = t; i < 768; i += 256) {
            int bb = i / 384, kk = i - bb * 384;
            xs[bb * 384 + kk] = x[bb * 3072 + by * 384 + kk];
        }
        // init global mins while loads are in flight
        #pragma unroll
        for (int i = 0; i < 4; ++i) g_aminU[blk * 1024 + i * 256 + t] = 0xFFFFFFFFu;
        if (t < 16) g_bminU[blk * 16 + t] = 0xFFFFFFFFu;
        if (blk == 0 && t == 0) g_lossA = 0.0f;
        __syncthreads();
        float a0 = 0.0f, a1 = 0.0f;
        int k0 = by * 384 + w * 48, kl0 = w * 48;
        #pragma unroll 16
        for (int j = 0; j < 48; ++j) {
            float wt = We1[(k0 + j) * 512 + col];
            a0 = fmaf(xs[kl0 + j],       wt, a0);
            a1 = fmaf(xs[384 + kl0 + j], wt, a1);
        }
        red[t]       = a0;
        red[256 + t] = a1;
        __syncthreads();
        if (t < 64) {
            int bb = t >> 5, ll = t & 31;
            float s = 0.0f;
            #pragma unroll
            for (int r = 0; r < 8; ++r) s += red[bb * 256 + r * 32 + ll];
            g_p1[(by * 2 + bb) * 512 + bx * 32 + ll] = s;
        }
    }
    gbar(128);

    // ===== P1: h1 combine + h2 partials (8 blocks) ==========================
    if (blk < 8) {
        float* h1loc = (float*)sraw;        // [128]
        float* hp    = h1loc + 128;         // [2][128]
        int b = blk & 1, ks = blk >> 1;     // ks in 0..3
        int k0 = ks * 128;
        if (t < 128) {
            float s = be1[k0 + t];
            #pragma unroll
            for (int sl = 0; sl < 8; ++sl) s += g_p1[(sl * 2 + b) * 512 + k0 + t];
            h1loc[t] = fmaxf(s, 0.0f);
        }
        __syncthreads();
        int sub = t >> 7, col = t & 127;
        float acc = 0.0f;
        int kk0 = sub * 64;
        #pragma unroll 16
        for (int j = 0; j < 64; ++j)
            acc = fmaf(h1loc[kk0 + j], We2[(k0 + kk0 + j) * 128 + col], acc);
        hp[sub * 128 + col] = acc;
        __syncthreads();
        if (t < 128) g_p2[(ks * 2 + b) * 128 + t] = hp[t] + hp[128 + t];
    }
    gbar(256);

    // ===== P2: h2 combine + z (2 blocks) ====================================
    if (blk < 2) {
        float* h2s = (float*)sraw;          // [128]
        float* zp  = h2s + 128;             // [4][64]
        int b = blk;
        if (t < 128) {
            float s = be2[t];
            #pragma unroll
            for (int ks = 0; ks < 4; ++ks) s += g_p2[(ks * 2 + b) * 128 + t];
            h2s[t] = fmaxf(s, 0.0f);
        }
        __syncthreads();
        int ksl = t >> 6, col = t & 63;
        float acc = 0.0f;
        #pragma unroll
        for (int j = 0; j < 32; ++j)
            acc = fmaf(h2s[ksl * 32 + j], We3[(ksl * 32 + j) * 64 + col], acc);
        zp[ksl * 64 + col] = acc;
        __syncthreads();
        if (t < 64)
            g_z[b * 64 + t] = fmaxf(zp[t] + zp[64 + t] + zp[128 + t] + zp[192 + t] + be3[t], 0.0f);
    }
    gbar(384);

    // ===== P3: dec1 + dec2 fused (64 blocks, 2 rows each) ===================
    if (blk < 64) {
        u64*   d1p = (u64*)sraw;            // [128]
        float* zi  = (float*)(sraw + 1024); // [2][67]
        float* d1s = (float*)(sraw + 1600); // [2][128]
        int r0 = blk * 2;
        int b  = r0 >> 6;
        if (t < 134) {
            int rw = (t >= 67), i = t - rw * 67;
            int g = (r0 + rw) & 63;
            zi[rw * 67 + i] = (i < 64) ? g_z[b * 64 + i] : grid_pts[g * 3 + (i - 64)];
        }
        __syncthreads();
        {
            int rw = t >> 7, col = t & 127;
            float acc = bd1[col];
            #pragma unroll
            for (int k = 0; k < 67; ++k)
                acc = fmaf(zi[rw * 67 + k], Wd1[k * 128 + col], acc);
            d1s[rw * 128 + col] = fmaxf(acc, 0.0f);
        }
        __syncthreads();
        if (t < 128) d1p[t] = pk2(d1s[t], d1s[128 + t]);
        __syncthreads();
        u64 a0 = 0ull, a1 = 0ull;
        #pragma unroll 8
        for (int k = 0; k < 128; ++k) {
            float2 w = *(const float2*)&Wd2[k * 512 + 2 * t];
            u64 dp = d1p[k];
            a0 = fma2_(dp, pk2(w.x, w.x), a0);
            a1 = fma2_(dp, pk2(w.y, w.y), a1);
        }
        float2 v0 = upk(a0), v1 = upk(a1);
        float b0 = bd2[2 * t], b1 = bd2[2 * t + 1];
        *(float2*)&g_d2[(r0 + 0) * 512 + 2 * t] =
            make_float2(fmaxf(v0.x + b0, 0.0f), fmaxf(v1.x + b1, 0.0f));
        *(float2*)&g_d2[(r0 + 1) * 512 + 2 * t] =
            make_float2(fmaxf(v0.y + b0, 0.0f), fmaxf(v1.y + b1, 0.0f));
    }
    gbar(512);

    // ===== P4: dec3 [128,512]x[512,3072] + tanh (96 blocks) =================
    if (blk < 96) {
        float* As = (float*)sraw;           // [512][20] padded
        int rg = blk / 12, cg = blk - rg * 12;   // 8 rowgroups x 12 colgroups
        int r0 = rg * 16;
        int col = cg * 256 + t;
        for (int idx = t; idx < 8192; idx += 256) {
            int r = idx >> 9, k = idx & 511;
            As[k * 20 + r] = g_d2[(r0 + r) * 512 + k];
        }
        __syncthreads();
        u64 acc[8];
        #pragma unroll
        for (int p = 0; p < 8; ++p) acc[p] = 0ull;
        #pragma unroll 4
        for (int k = 0; k < 512; ++k) {
            float w = Wd3[k * 3072 + col];
            u64 w2 = pk2(w, w);
            const ulonglong2* ap = (const ulonglong2*)&As[k * 20];
            ulonglong2 q0 = ap[0], q1 = ap[1];
            acc[0] = fma2_(q0.x, w2, acc[0]);
            acc[1] = fma2_(q0.y, w2, acc[1]);
            acc[2] = fma2_(q1.x, w2, acc[2]);
            acc[3] = fma2_(q1.y, w2, acc[3]);
            ulonglong2 q2 = ap[2], q3 = ap[3];
            acc[4] = fma2_(q2.x, w2, acc[4]);
            acc[5] = fma2_(q2.y, w2, acc[5]);
            acc[6] = fma2_(q3.x, w2, acc[6]);
            acc[7] = fma2_(q3.y, w2, acc[7]);
        }
        float bb = bd3[col];
        #pragma unroll
        for (int p = 0; p < 8; ++p) {
            float2 v = upk(acc[p]);
            g_Y[(r0 + 2 * p + 0) * 3072 + col] = tanhf(v.x + bb);
            g_Y[(r0 + 2 * p + 1) * 3072 + col] = tanhf(v.y + bb);
        }
    }
    gbar(640);

    // ===== P5: symmetric chamfer (all 128 blocks) ===========================
    // v = 0.5|y|^2 + 0.5|s|^2 - y.s  (= 0.5*d2, symmetric for both directions)
    {
        u64*      sd    = (u64*)sraw;              // [256][4]
        unsigned* sbmin = (unsigned*)(sraw + 8192);
        int b     = blk >> 6;
        int inner = blk & 63;
        int yt = inner >> 2, ms = inner & 3;
        int wid = t >> 5, lane = t & 31;
        int m0 = ms * 256;
        {
            int m = m0 + t;
            float sx = x[(b * 1024 + m) * 3 + 0];
            float sy = x[(b * 1024 + m) * 3 + 1];
            float sz = x[(b * 1024 + m) * 3 + 2];
            float hs = 0.5f * (sx * sx + sy * sy + sz * sz);
            sd[t * 4 + 0] = pk2(-sx, -sx);
            sd[t * 4 + 1] = pk2(-sy, -sy);
            sd[t * 4 + 2] = pk2(-sz, -sz);
            sd[t * 4 + 3] = pk2(hs, hs);
            sbmin[t] = 0xFFFFFFFFu;
        }
        int nbase = b * 65536 + yt * 4096;
        float yv[16][3], hyv[16];
        #pragma unroll
        for (int j = 0; j < 16; ++j) {
            int n = nbase + j * 256 + t;
            float a0 = g_Y[n * 3 + 0], a1 = g_Y[n * 3 + 1], a2 = g_Y[n * 3 + 2];
            yv[j][0] = a0; yv[j][1] = a1; yv[j][2] = a2;
            hyv[j] = 0.5f * (a0 * a0 + a1 * a1 + a2 * a2);
        }
        u64 px[8], py[8], pz[8], ph[8];
        #pragma unroll
        for (int p = 0; p < 8; ++p) {
            px[p] = pk2(yv[2 * p][0], yv[2 * p + 1][0]);
            py[p] = pk2(yv[2 * p][1], yv[2 * p + 1][1]);
            pz[p] = pk2(yv[2 * p][2], yv[2 * p + 1][2]);
            ph[p] = pk2(hyv[2 * p], hyv[2 * p + 1]);
        }
        float amin[16];
        #pragma unroll
        for (int j = 0; j < 16; ++j) amin[j] = 3.4e38f;
        __syncthreads();

        int moff = (wid * 32) & 255;
        for (int mi = 0; mi < 256; ++mi) {
            int mm = (mi + moff) & 255;
            ulonglong2 q0 = *(const ulonglong2*)&sd[mm * 4];
            ulonglong2 q1 = *(const ulonglong2*)&sd[mm * 4 + 2];
            u64 nx = q0.x, ny = q0.y, nz = q1.x, hs2 = q1.y;
            float bcur = 3.4e38f;
            #pragma unroll
            for (int p = 0; p < 8; ++p) {
                u64 v2 = fma2_(px[p], nx, fma2_(py[p], ny, fma2_(pz[p], nz, add2_(ph[p], hs2))));
                float2 v = upk(v2);
                amin[2 * p + 0] = fminf(amin[2 * p + 0], v.x);
                amin[2 * p + 1] = fminf(amin[2 * p + 1], v.y);
                bcur = fminf(bcur, fminf(v.x, v.y));
            }
            #pragma unroll
            for (int s = 16; s > 0; s >>= 1)
                bcur = fminf(bcur, __shfl_xor_sync(0xFFFFFFFFu, bcur, s));
            if (lane == 0) atomicMin(&sbmin[mm], f2key(bcur));
        }
        __syncthreads();

        atomicMin(&g_bminU[b * 1024 + m0 + t], sbmin[t]);
        #pragma unroll
        for (int j = 0; j < 16; ++j) {
            int n = nbase + j * 256 + t;
            atomicMin(&g_aminU[n], f2key(amin[j]));
        }
    }
    gbar(768);

    // ===== P6: final reduce (all 128 blocks) ================================
    {
        float* red = (float*)sraw;
        float s = 0.0f;
        #pragma unroll
        for (int i = 0; i < 4; ++i) s += key2f(g_aminU[blk * 1024 + i * 256 + t]);
        if (t < 16) s += key2f(g_bminU[blk * 16 + t]);
        red[t] = s;
        __syncthreads();
        #pragma unroll
        for (int st = 128; st > 0; st >>= 1) {
            if (t < st) red[t] += red[t + st];
            __syncthreads();
        }
        if (t == 0) atomicAdd(&g_lossA, red[0]);
    }
    gbar(896);

    // ===== epilogue: write output, drain, self-reset barrier state ==========
    if (t == 0) {
        atomicAdd(&g_done, 1u);
        if (blk == 0) {
            out[0] = 2.0f * g_lossA;
            while (*(volatile unsigned*)&g_done < 128u) __nanosleep(32);
            g_barcnt = 0u;
            g_done   = 0u;
            __threadfence();
        }
    }
}

// ---------------- launch ----------------------------------------------------
extern "C" void kernel_launch(void* const* d_in, const int* in_sizes, int n_in,
                              void* d_out, int out_size) {
    const float* x    = (const float*)d_in[0];
    const float* grid = (const float*)d_in[1];
    const float* We1  = (const float*)d_in[2];
    const float* be1  = (const float*)d_in[3];
    const float* We2  = (const float*)d_in[4];
    const float* be2  = (const float*)d_in[5];
    const float* We3  = (const float*)d_in[6];
    const float* be3  = (const float*)d_in[7];
    const float* Wd1  = (const float*)d_in[8];
    const float* bd1  = (const float*)d_in[9];
    const float* Wd2  = (const float*)d_in[10];
    const float* bd2  = (const float*)d_in[11];
    const float* Wd3  = (const float*)d_in[12];
    const float* bd3  = (const float*)d_in[13];
    float* out = (float*)d_out;

    k_mega<<<128, 256>>>(x, grid, We1, be1, We2, be2, We3, be3,
                         Wd1, bd1, Wd2, bd2, Wd3, bd3, out);
}

// round 4
// speedup vs baseline: 2.2475x; 1.3088x over previous
#include <cuda_runtime.h>

typedef unsigned long long u64;

// ---------------- scratch (device globals) ---------------------------------
__device__ float g_p1[8 * 2 * 512];       // enc1 k-partials
__device__ float g_p2[4 * 2 * 128];       // enc2 h2 k-partials
__device__ float g_z[2 * 64];
__device__ float g_d2[2 * 64 * 512];
__device__ float g_Y[2 * 65536 * 3];
__device__ float g_lossA;
__device__ unsigned g_aminU[2 * 65536];
__device__ unsigned g_bminU[2 * 1024];
__device__ unsigned g_barcnt;
__device__ unsigned g_done;

// ---------------- f32x2 helpers -------------------------------------------
__device__ __forceinline__ u64 pk2(float a, float b) {
    u64 r; asm("mov.b64 %0, {%1,%2};" : "=l"(r) : "f"(a), "f"(b)); return r;
}
__device__ __forceinline__ float2 upk(u64 v) {
    float2 r; asm("mov.b64 {%0,%1}, %2;" : "=f"(r.x), "=f"(r.y) : "l"(v)); return r;
}
__device__ __forceinline__ u64 fma2_(u64 a, u64 b, u64 c) {
    u64 d; asm("fma.rn.f32x2 %0, %1, %2, %3;" : "=l"(d) : "l"(a), "l"(b), "l"(c)); return d;
}
__device__ __forceinline__ u64 add2_(u64 a, u64 b) {
    u64 d; asm("add.rn.f32x2 %0, %1, %2;" : "=l"(d) : "l"(a), "l"(b)); return d;
}
__device__ __forceinline__ unsigned f2key(float f) {
    unsigned b = __float_as_uint(f);
    return b ^ ((unsigned)((int)b >> 31) | 0x80000000u);
}
__device__ __forceinline__ float key2f(unsigned k) {
    unsigned b = (k & 0x80000000u) ? (k ^ 0x80000000u) : ~k;
    return __uint_as_float(b);
}

// ---------------- grid-wide spin barrier -----------------------------------
__device__ __forceinline__ void gbar(unsigned target) {
    __threadfence();
    __syncthreads();
    if (threadIdx.x == 0) {
        atomicAdd(&g_barcnt, 1u);
        while (*(volatile unsigned*)&g_barcnt < target) __nanosleep(32);
    }
    __syncthreads();
}

// ---------------- the megakernel -------------------------------------------
__global__ void __launch_bounds__(512, 1) k_mega(
    const float* __restrict__ x,   const float* __restrict__ grid_pts,
    const float* __restrict__ We1, const float* __restrict__ be1,
    const float* __restrict__ We2, const float* __restrict__ be2,
    const float* __restrict__ We3, const float* __restrict__ be3,
    const float* __restrict__ Wd1, const float* __restrict__ bd1,
    const float* __restrict__ Wd2, const float* __restrict__ bd2,
    const float* __restrict__ Wd3, const float* __restrict__ bd3,
    float* __restrict__ out)
{
    __shared__ __align__(16) unsigned char sraw[20608];
    const int t   = threadIdx.x;
    const int blk = blockIdx.x;
    const int lane = t & 31;
    const int wid  = t >> 5;

    // ===== P0: enc1 partials (128 blocks, 16 warps x 24k) + init ===========
    {
        float* xs  = (float*)sraw;          // [2][384]
        float* red = xs + 768;              // [2][512]
        int bx = blk >> 3, by = blk & 7;
        int col = bx * 32 + lane;
        for (int i = t; i < 768; i += 512) {
            int bb = (i >= 384), kk = i - bb * 384;
            xs[bb * 384 + kk] = x[bb * 3072 + by * 384 + kk];
        }
        g_aminU[blk * 1024 + t]       = 0xFFFFFFFFu;
        g_aminU[blk * 1024 + 512 + t] = 0xFFFFFFFFu;
        if (t < 16) g_bminU[blk * 16 + t] = 0xFFFFFFFFu;
        if (blk == 0 && t == 0) g_lossA = 0.0f;
        __syncthreads();
        float a0 = 0.0f, a1 = 0.0f;
        int k0 = by * 384 + wid * 24, kl0 = wid * 24;
        #pragma unroll
        for (int j = 0; j < 24; ++j) {
            float wt = We1[(k0 + j) * 512 + col];
            a0 = fmaf(xs[kl0 + j],       wt, a0);
            a1 = fmaf(xs[384 + kl0 + j], wt, a1);
        }
        red[t]       = a0;
        red[512 + t] = a1;
        __syncthreads();
        if (t < 64) {
            int bb = t >> 5, ll = t & 31;
            float s = 0.0f;
            #pragma unroll
            for (int r = 0; r < 16; ++r) s += red[bb * 512 + r * 32 + ll];
            g_p1[(by * 2 + bb) * 512 + bx * 32 + ll] = s;
        }
    }
    gbar(128);

    // ===== P1: h1 combine + h2 partials (8 blocks) ==========================
    if (blk < 8) {
        float* h1loc = (float*)sraw;        // [128]
        float* hp    = h1loc + 128;         // [4][128]
        int b = blk & 1, ks = blk >> 1;
        int k0 = ks * 128;
        if (t < 128) {
            float s = be1[k0 + t];
            #pragma unroll
            for (int sl = 0; sl < 8; ++sl) s += g_p1[(sl * 2 + b) * 512 + k0 + t];
            h1loc[t] = fmaxf(s, 0.0f);
        }
        __syncthreads();
        int sub = t >> 7, col = t & 127;
        float acc = 0.0f;
        #pragma unroll
        for (int j = 0; j < 32; ++j)
            acc = fmaf(h1loc[sub * 32 + j], We2[(k0 + sub * 32 + j) * 128 + col], acc);
        hp[sub * 128 + col] = acc;
        __syncthreads();
        if (t < 128) g_p2[(ks * 2 + b) * 128 + t] = hp[t] + hp[128 + t] + hp[256 + t] + hp[384 + t];
    }
    gbar(256);

    // ===== P2: h2 combine + z (2 blocks) ====================================
    if (blk < 2) {
        float* h2s = (float*)sraw;          // [128]
        float* zp  = h2s + 128;             // [8][64]
        int b = blk;
        if (t < 128) {
            float s = be2[t];
            #pragma unroll
            for (int ks = 0; ks < 4; ++ks) s += g_p2[(ks * 2 + b) * 128 + t];
            h2s[t] = fmaxf(s, 0.0f);
        }
        __syncthreads();
        int ksl = t >> 6, col = t & 63;
        float acc = 0.0f;
        #pragma unroll
        for (int j = 0; j < 16; ++j)
            acc = fmaf(h2s[ksl * 16 + j], We3[(ksl * 16 + j) * 64 + col], acc);
        zp[ksl * 64 + col] = acc;
        __syncthreads();
        if (t < 64) {
            float s = be3[t];
            #pragma unroll
            for (int sl = 0; sl < 8; ++sl) s += zp[sl * 64 + t];
            g_z[b * 64 + t] = fmaxf(s, 0.0f);
        }
    }
    gbar(384);

    // ===== P3: dec1 + dec2 fused (64 blocks, 2 rows each) ===================
    if (blk < 64) {
        u64*   d1p = (u64*)sraw;            // [128]
        float* zi  = (float*)(sraw + 1024); // [2][67]
        float* d1s = (float*)(sraw + 1664); // [2][128]
        int r0 = blk * 2;
        int b  = r0 >> 6;
        if (t < 134) {
            int rw = (t >= 67), i = t - rw * 67;
            int g = (r0 + rw) & 63;
            zi[rw * 67 + i] = (i < 64) ? g_z[b * 64 + i] : grid_pts[g * 3 + (i - 64)];
        }
        __syncthreads();
        if (t < 256) {
            int rw = t >> 7, col = t & 127;
            float acc = bd1[col];
            #pragma unroll
            for (int k = 0; k < 67; ++k)
                acc = fmaf(zi[rw * 67 + k], Wd1[k * 128 + col], acc);
            d1s[rw * 128 + col] = fmaxf(acc, 0.0f);
        }
        __syncthreads();
        if (t < 128) d1p[t] = pk2(d1s[t], d1s[128 + t]);
        __syncthreads();
        u64 acc = 0ull;
        #pragma unroll 8
        for (int k = 0; k < 128; ++k) {
            float w = Wd2[k * 512 + t];
            acc = fma2_(d1p[k], pk2(w, w), acc);
        }
        float2 v = upk(acc);
        float bb = bd2[t];
        g_d2[(r0 + 0) * 512 + t] = fmaxf(v.x + bb, 0.0f);
        g_d2[(r0 + 1) * 512 + t] = fmaxf(v.y + bb, 0.0f);
    }
    gbar(512);

    // ===== P4: dec3 [128,512]x[512,3072] + tanh (128 blocks) ================
    {
        float* As = (float*)sraw;           // [512][10] padded
        int rg = blk >> 3, cg = blk & 7;    // 16 rowgroups(8) x 8 colgroups(384)
        int r0 = rg * 8;
        for (int idx = t; idx < 4096; idx += 512) {
            int r = idx & 7, k = idx >> 3;
            As[k * 10 + r] = g_d2[(r0 + r) * 512 + k];
        }
        __syncthreads();
        if (t < 384) {
            int col = cg * 384 + t;
            u64 acc0 = 0ull, acc1 = 0ull, acc2 = 0ull, acc3 = 0ull;
            #pragma unroll 4
            for (int k = 0; k < 512; ++k) {
                float w = Wd3[k * 3072 + col];
                u64 w2 = pk2(w, w);
                const ulonglong2* ap = (const ulonglong2*)&As[k * 10];
                ulonglong2 q0 = ap[0], q1 = ap[1];
                acc0 = fma2_(q0.x, w2, acc0);
                acc1 = fma2_(q0.y, w2, acc1);
                acc2 = fma2_(q1.x, w2, acc2);
                acc3 = fma2_(q1.y, w2, acc3);
            }
            float bb = bd3[col];
            float2 v0 = upk(acc0), v1 = upk(acc1), v2 = upk(acc2), v3 = upk(acc3);
            g_Y[(r0 + 0) * 3072 + col] = tanhf(v0.x + bb);
            g_Y[(r0 + 1) * 3072 + col] = tanhf(v0.y + bb);
            g_Y[(r0 + 2) * 3072 + col] = tanhf(v1.x + bb);
            g_Y[(r0 + 3) * 3072 + col] = tanhf(v1.y + bb);
            g_Y[(r0 + 4) * 3072 + col] = tanhf(v2.x + bb);
            g_Y[(r0 + 5) * 3072 + col] = tanhf(v2.y + bb);
            g_Y[(r0 + 6) * 3072 + col] = tanhf(v3.x + bb);
            g_Y[(r0 + 7) * 3072 + col] = tanhf(v3.y + bb);
        }
    }
    gbar(640);

    // ===== P5: symmetric chamfer, systolic ring =============================
    // v = hy + hs - y.s (= 0.5*d2). S + bmin rotate through lanes in registers.
    {
        unsigned* sbmin = (unsigned*)sraw;   // [256]
        int b = blk >> 6, inner = blk & 63;
        int yt = inner >> 2, ms = inner & 3;
        if (t < 256) sbmin[t] = 0xFFFFFFFFu;

        int nbase = b * 65536 + yt * 4096 + wid * 256;
        float yx[8], yy[8], yz[8], h8[8];
        #pragma unroll
        for (int j = 0; j < 8; ++j) {
            int n = nbase + j * 32 + lane;
            float a0 = g_Y[n * 3 + 0], a1 = g_Y[n * 3 + 1], a2 = g_Y[n * 3 + 2];
            yx[j] = a0; yy[j] = a1; yz[j] = a2;
            h8[j] = 0.5f * (a0 * a0 + a1 * a1 + a2 * a2);
        }
        u64 px[4], py[4], pz[4], ph[4];
        #pragma unroll
        for (int p = 0; p < 4; ++p) {
            px[p] = pk2(yx[2 * p], yx[2 * p + 1]);
            py[p] = pk2(yy[2 * p], yy[2 * p + 1]);
            pz[p] = pk2(yz[2 * p], yz[2 * p + 1]);
            ph[p] = pk2(h8[2 * p], h8[2 * p + 1]);
        }
        float amin[8];
        #pragma unroll
        for (int j = 0; j < 8; ++j) amin[j] = 3.4e38f;
        __syncthreads();

        for (int g = 0; g < 8; ++g) {
            int m = b * 1024 + ms * 256 + g * 32 + lane;
            float sx = x[m * 3 + 0], sy = x[m * 3 + 1], sz = x[m * 3 + 2];
            float nx = -sx, ny = -sy, nz = -sz;
            float hs = 0.5f * (sx * sx + sy * sy + sz * sz);
            float bacc = 3.4e38f;
            #pragma unroll 8
            for (int step = 0; step < 32; ++step) {
                u64 nx2 = pk2(nx, nx), ny2 = pk2(ny, ny);
                u64 nz2 = pk2(nz, nz), hs2 = pk2(hs, hs);
                float tm[4];
                #pragma unroll
                for (int p = 0; p < 4; ++p) {
                    // v = hy - y.s ; a = v + hs (full distance/2)
                    u64 v2 = fma2_(px[p], nx2, fma2_(py[p], ny2, fma2_(pz[p], nz2, ph[p])));
                    u64 a2 = add2_(v2, hs2);
                    float2 va = upk(a2);
                    amin[2 * p + 0] = fminf(amin[2 * p + 0], va.x);
                    amin[2 * p + 1] = fminf(amin[2 * p + 1], va.y);
                    float2 vv = upk(v2);
                    tm[p] = fminf(vv.x, vv.y);
                }
                float tmin = fminf(fminf(tm[0], tm[1]), fminf(tm[2], tm[3]));
                bacc = fminf(bacc, tmin + hs);
                int src = (lane + 1) & 31;
                nx   = __shfl_sync(0xffffffffu, nx,   src);
                ny   = __shfl_sync(0xffffffffu, ny,   src);
                nz   = __shfl_sync(0xffffffffu, nz,   src);
                hs   = __shfl_sync(0xffffffffu, hs,   src);
                bacc = __shfl_sync(0xffffffffu, bacc, src);
            }
            atomicMin(&sbmin[g * 32 + lane], f2key(bacc));
        }
        __syncthreads();
        if (t < 256) atomicMin(&g_bminU[b * 1024 + ms * 256 + t], sbmin[t]);
        #pragma unroll
        for (int j = 0; j < 8; ++j) {
            int n = nbase + j * 32 + lane;
            atomicMin(&g_aminU[n], f2key(amin[j]));
        }
    }
    gbar(768);

    // ===== P6: final reduce (128 blocks) ====================================
    {
        float* red = (float*)sraw;
        float s = key2f(g_aminU[blk * 1024 + t]) + key2f(g_aminU[blk * 1024 + 512 + t]);
        if (t < 16) s += key2f(g_bminU[blk * 16 + t]);
        red[t] = s;
        __syncthreads();
        #pragma unroll
        for (int st = 256; st > 0; st >>= 1) {
            if (t < st) red[t] += red[t + st];
            __syncthreads();
        }
        if (t == 0) atomicAdd(&g_lossA, red[0]);
    }
    gbar(896);

    // ===== epilogue: write output, drain, self-reset ========================
    if (t == 0) {
        atomicAdd(&g_done, 1u);
        if (blk == 0) {
            out[0] = 2.0f * g_lossA;
            while (*(volatile unsigned*)&g_done < 128u) __nanosleep(32);
            g_barcnt = 0u;
            g_done   = 0u;
            __threadfence();
        }
    }
}

// ---------------- launch ----------------------------------------------------
extern "C" void kernel_launch(void* const* d_in, const int* in_sizes, int n_in,
                              void* d_out, int out_size) {
    const float* x    = (const float*)d_in[0];
    const float* grid = (const float*)d_in[1];
    const float* We1  = (const float*)d_in[2];
    const float* be1  = (const float*)d_in[3];
    const float* We2  = (const float*)d_in[4];
    const float* be2  = (const float*)d_in[5];
    const float* We3  = (const float*)d_in[6];
    const float* be3  = (const float*)d_in[7];
    const float* Wd1  = (const float*)d_in[8];
    const float* bd1  = (const float*)d_in[9];
    const float* Wd2  = (const float*)d_in[10];
    const float* bd2  = (const float*)d_in[11];
    const float* Wd3  = (const float*)d_in[12];
    const float* bd3  = (const float*)d_in[13];
    float* out = (float*)d_out;

    k_mega<<<128, 512>>>(x, grid, We1, be1, We2, be2, We3, be3,
                         Wd1, bd1, Wd2, bd2, Wd3, bd3, out);
}

// round 5
// speedup vs baseline: 2.2492x; 1.0008x over previous
#include <cuda_runtime.h>

typedef unsigned long long u64;

// ---------------- scratch (device globals) ---------------------------------
__device__ float g_p1[8 * 2 * 512];       // enc1 k-partials
__device__ float g_z[2 * 64];
__device__ float g_d2[2 * 64 * 512];
__device__ float g_Y[2 * 65536 * 3];
__device__ float g_lossA;
__device__ unsigned g_aminU[2 * 65536];
__device__ unsigned g_bminU[2 * 1024];
__device__ unsigned g_barcnt;
__device__ unsigned g_done;

// ---------------- f32x2 helpers -------------------------------------------
__device__ __forceinline__ u64 pk2(float a, float b) {
    u64 r; asm("mov.b64 %0, {%1,%2};" : "=l"(r) : "f"(a), "f"(b)); return r;
}
__device__ __forceinline__ float2 upk(u64 v) {
    float2 r; asm("mov.b64 {%0,%1}, %2;" : "=f"(r.x), "=f"(r.y) : "l"(v)); return r;
}
__device__ __forceinline__ u64 fma2_(u64 a, u64 b, u64 c) {
    u64 d; asm("fma.rn.f32x2 %0, %1, %2, %3;" : "=l"(d) : "l"(a), "l"(b), "l"(c)); return d;
}
__device__ __forceinline__ u64 add2_(u64 a, u64 b) {
    u64 d; asm("add.rn.f32x2 %0, %1, %2;" : "=l"(d) : "l"(a), "l"(b)); return d;
}
__device__ __forceinline__ unsigned f2key(float f) {
    unsigned b = __float_as_uint(f);
    return b ^ ((unsigned)((int)b >> 31) | 0x80000000u);
}
__device__ __forceinline__ float key2f(unsigned k) {
    unsigned b = (k & 0x80000000u) ? (k ^ 0x80000000u) : ~k;
    return __uint_as_float(b);
}

// ---------------- grid-wide spin barrier -----------------------------------
__device__ __forceinline__ void gbar(unsigned target) {
    __threadfence();
    __syncthreads();
    if (threadIdx.x == 0) {
        atomicAdd(&g_barcnt, 1u);
        while (*(volatile unsigned*)&g_barcnt < target) __nanosleep(32);
    }
    __syncthreads();
}

// ---------------- the megakernel -------------------------------------------
__global__ void __launch_bounds__(512, 1) k_mega(
    const float* __restrict__ x,   const float* __restrict__ grid_pts,
    const float* __restrict__ We1, const float* __restrict__ be1,
    const float* __restrict__ We2, const float* __restrict__ be2,
    const float* __restrict__ We3, const float* __restrict__ be3,
    const float* __restrict__ Wd1, const float* __restrict__ bd1,
    const float* __restrict__ Wd2, const float* __restrict__ bd2,
    const float* __restrict__ Wd3, const float* __restrict__ bd3,
    float* __restrict__ out)
{
    __shared__ __align__(16) unsigned char sraw[20608];
    const int t    = threadIdx.x;
    const int blk  = blockIdx.x;
    const int lane = t & 31;
    const int wid  = t >> 5;

    // ===== P0: enc1 partials (128 blocks, 16 warps x 24k) + init ===========
    {
        float* xs  = (float*)sraw;          // [2][384]
        float* red = xs + 768;              // [2][512]
        int bx = blk >> 3, by = blk & 7;
        int col = bx * 32 + lane;
        for (int i = t; i < 768; i += 512) {
            int bb = (i >= 384), kk = i - bb * 384;
            xs[bb * 384 + kk] = x[bb * 3072 + by * 384 + kk];
        }
        g_aminU[blk * 1024 + t]       = 0xFFFFFFFFu;
        g_aminU[blk * 1024 + 512 + t] = 0xFFFFFFFFu;
        if (t < 16) g_bminU[blk * 16 + t] = 0xFFFFFFFFu;
        if (blk == 0 && t == 0) g_lossA = 0.0f;
        __syncthreads();
        float a0 = 0.0f, a1 = 0.0f;
        int k0 = by * 384 + wid * 24, kl0 = wid * 24;
        #pragma unroll
        for (int j = 0; j < 24; ++j) {
            float wt = We1[(k0 + j) * 512 + col];
            a0 = fmaf(xs[kl0 + j],       wt, a0);
            a1 = fmaf(xs[384 + kl0 + j], wt, a1);
        }
        red[t]       = a0;
        red[512 + t] = a1;
        __syncthreads();
        if (t < 64) {
            int bb = t >> 5, ll = t & 31;
            float s = 0.0f;
            #pragma unroll
            for (int r = 0; r < 16; ++r) s += red[bb * 512 + r * 32 + ll];
            g_p1[(by * 2 + bb) * 512 + bx * 32 + ll] = s;
        }
    }
    gbar(128);

    // ===== P1: encoder layers 1-combine, 2, 3 (2 blocks, 512 thr) ==========
    if (blk < 2) {
        float* h1s = (float*)sraw;          // [512]
        float* hp  = h1s + 512;             // [4][128]
        float* h2s = hp + 512;              // [128]
        float* zp  = h2s + 128;             // [8][64]
        int b = blk;
        {
            float s = be1[t];
            #pragma unroll
            for (int sl = 0; sl < 8; ++sl) s += g_p1[(sl * 2 + b) * 512 + t];
            h1s[t] = fmaxf(s, 0.0f);
        }
        __syncthreads();
        {
            int ks = t >> 7, col = t & 127;
            float acc = 0.0f;
            #pragma unroll
            for (int j = 0; j < 32; ++j) {
                int k = ks * 128 + j * 4;
                acc = fmaf(h1s[k + 0], We2[(k + 0) * 128 + col], acc);
                acc = fmaf(h1s[k + 1], We2[(k + 1) * 128 + col], acc);
                acc = fmaf(h1s[k + 2], We2[(k + 2) * 128 + col], acc);
                acc = fmaf(h1s[k + 3], We2[(k + 3) * 128 + col], acc);
            }
            hp[ks * 128 + col] = acc;
        }
        __syncthreads();
        if (t < 128)
            h2s[t] = fmaxf(hp[t] + hp[128 + t] + hp[256 + t] + hp[384 + t] + be2[t], 0.0f);
        __syncthreads();
        {
            int ks = t >> 6, col = t & 63;
            float acc = 0.0f;
            #pragma unroll
            for (int j = 0; j < 16; ++j)
                acc = fmaf(h2s[ks * 16 + j], We3[(ks * 16 + j) * 64 + col], acc);
            zp[ks * 64 + col] = acc;
        }
        __syncthreads();
        if (t < 64) {
            float s = be3[t];
            #pragma unroll
            for (int sl = 0; sl < 8; ++sl) s += zp[sl * 64 + t];
            g_z[b * 64 + t] = fmaxf(s, 0.0f);
        }
    }
    gbar(256);

    // ===== P2: dec1 + dec2 fused (64 blocks, 2 rows each) ===================
    if (blk < 64) {
        u64*   d1p = (u64*)sraw;            // [128]
        float* zi  = (float*)(sraw + 1024); // [2][67]
        float* d1s = (float*)(sraw + 1664); // [2][128]
        int r0 = blk * 2;
        int b  = r0 >> 6;
        if (t < 134) {
            int rw = (t >= 67), i = t - rw * 67;
            int g = (r0 + rw) & 63;
            zi[rw * 67 + i] = (i < 64) ? g_z[b * 64 + i] : grid_pts[g * 3 + (i - 64)];
        }
        __syncthreads();
        if (t < 256) {
            int rw = t >> 7, col = t & 127;
            float acc = bd1[col];
            #pragma unroll
            for (int k = 0; k < 67; ++k)
                acc = fmaf(zi[rw * 67 + k], Wd1[k * 128 + col], acc);
            d1s[rw * 128 + col] = fmaxf(acc, 0.0f);
        }
        __syncthreads();
        if (t < 128) d1p[t] = pk2(d1s[t], d1s[128 + t]);
        __syncthreads();
        u64 acc = 0ull;
        #pragma unroll 8
        for (int k = 0; k < 128; ++k) {
            float w = Wd2[k * 512 + t];
            acc = fma2_(d1p[k], pk2(w, w), acc);
        }
        float2 v = upk(acc);
        float bb = bd2[t];
        g_d2[(r0 + 0) * 512 + t] = fmaxf(v.x + bb, 0.0f);
        g_d2[(r0 + 1) * 512 + t] = fmaxf(v.y + bb, 0.0f);
    }
    gbar(384);

    // ===== P3: dec3 [128,512]x[512,3072] + tanh (128 blocks) ================
    {
        float* As = (float*)sraw;           // [512][10] padded
        int rg = blk >> 3, cg = blk & 7;    // 16 rowgroups(8) x 8 colgroups(384)
        int r0 = rg * 8;
        for (int idx = t; idx < 4096; idx += 512) {
            int r = idx & 7, k = idx >> 3;
            As[k * 10 + r] = g_d2[(r0 + r) * 512 + k];
        }
        __syncthreads();
        if (t < 384) {
            int col = cg * 384 + t;
            u64 acc0 = 0ull, acc1 = 0ull, acc2 = 0ull, acc3 = 0ull;
            #pragma unroll 4
            for (int k = 0; k < 512; ++k) {
                float w = Wd3[k * 3072 + col];
                u64 w2 = pk2(w, w);
                const ulonglong2* ap = (const ulonglong2*)&As[k * 10];
                ulonglong2 q0 = ap[0], q1 = ap[1];
                acc0 = fma2_(q0.x, w2, acc0);
                acc1 = fma2_(q0.y, w2, acc1);
                acc2 = fma2_(q1.x, w2, acc2);
                acc3 = fma2_(q1.y, w2, acc3);
            }
            float bb = bd3[col];
            float2 v0 = upk(acc0), v1 = upk(acc1), v2 = upk(acc2), v3 = upk(acc3);
            g_Y[(r0 + 0) * 3072 + col] = tanhf(v0.x + bb);
            g_Y[(r0 + 1) * 3072 + col] = tanhf(v0.y + bb);
            g_Y[(r0 + 2) * 3072 + col] = tanhf(v1.x + bb);
            g_Y[(r0 + 3) * 3072 + col] = tanhf(v1.y + bb);
            g_Y[(r0 + 4) * 3072 + col] = tanhf(v2.x + bb);
            g_Y[(r0 + 5) * 3072 + col] = tanhf(v2.y + bb);
            g_Y[(r0 + 6) * 3072 + col] = tanhf(v3.x + bb);
            g_Y[(r0 + 7) * 3072 + col] = tanhf(v3.y + bb);
        }
    }
    gbar(512);

    // ===== P4: symmetric chamfer, systolic ring (16 Y/lane, 128 S/block) ====
    // v = hy + hs - y.s (= 0.5*d2). S + bmin rotate through lanes in registers.
    {
        unsigned* sbmin = (unsigned*)sraw;   // [128]
        int b = blk >> 6, inner = blk & 63;
        int yt = inner >> 3, ms = inner & 7;
        if (t < 128) sbmin[t] = 0xFFFFFFFFu;

        int nbase = b * 65536 + yt * 8192 + wid * 512;
        u64 px[8], py[8], pz[8], ph[8];
        #pragma unroll
        for (int p = 0; p < 8; ++p) {
            int n0 = nbase + (2 * p) * 32 + lane;
            int n1 = nbase + (2 * p + 1) * 32 + lane;
            float a0 = g_Y[n0 * 3 + 0], a1 = g_Y[n0 * 3 + 1], a2 = g_Y[n0 * 3 + 2];
            float c0 = g_Y[n1 * 3 + 0], c1 = g_Y[n1 * 3 + 1], c2 = g_Y[n1 * 3 + 2];
            px[p] = pk2(a0, c0);
            py[p] = pk2(a1, c1);
            pz[p] = pk2(a2, c2);
            ph[p] = pk2(0.5f * (a0 * a0 + a1 * a1 + a2 * a2),
                        0.5f * (c0 * c0 + c1 * c1 + c2 * c2));
        }
        float amin[16];
        #pragma unroll
        for (int j = 0; j < 16; ++j) amin[j] = 3.4e38f;
        __syncthreads();

        int m0 = b * 1024 + ms * 128;
        for (int g = 0; g < 4; ++g) {
            int m = m0 + g * 32 + lane;
            float sx = x[m * 3 + 0], sy = x[m * 3 + 1], sz = x[m * 3 + 2];
            float nx = -sx, ny = -sy, nz = -sz;
            float hs = 0.5f * (sx * sx + sy * sy + sz * sz);
            float bacc = 3.4e38f;
            #pragma unroll 4
            for (int step = 0; step < 32; ++step) {
                u64 nx2 = pk2(nx, nx), ny2 = pk2(ny, ny);
                u64 nz2 = pk2(nz, nz), hs2 = pk2(hs, hs);
                float tm[8];
                #pragma unroll
                for (int p = 0; p < 8; ++p) {
                    u64 v2 = fma2_(px[p], nx2,
                             fma2_(py[p], ny2,
                             fma2_(pz[p], nz2, add2_(ph[p], hs2))));
                    float2 va = upk(v2);
                    amin[2 * p + 0] = fminf(amin[2 * p + 0], va.x);
                    amin[2 * p + 1] = fminf(amin[2 * p + 1], va.y);
                    tm[p] = fminf(va.x, va.y);
                }
                float t0 = fminf(fminf(tm[0], tm[1]), fminf(tm[2], tm[3]));
                float t1 = fminf(fminf(tm[4], tm[5]), fminf(tm[6], tm[7]));
                bacc = fminf(bacc, fminf(t0, t1));
                int src = (lane + 1) & 31;
                nx   = __shfl_sync(0xffffffffu, nx,   src);
                ny   = __shfl_sync(0xffffffffu, ny,   src);
                nz   = __shfl_sync(0xffffffffu, nz,   src);
                hs   = __shfl_sync(0xffffffffu, hs,   src);
                bacc = __shfl_sync(0xffffffffu, bacc, src);
            }
            atomicMin(&sbmin[g * 32 + lane], f2key(bacc));
        }
        __syncthreads();
        if (t < 128) atomicMin(&g_bminU[m0 + t], sbmin[t]);
        #pragma unroll
        for (int p = 0; p < 8; ++p) {
            atomicMin(&g_aminU[nbase + (2 * p) * 32 + lane],     f2key(amin[2 * p]));
            atomicMin(&g_aminU[nbase + (2 * p + 1) * 32 + lane], f2key(amin[2 * p + 1]));
        }
    }
    gbar(640);

    // ===== P5: final reduce + epilogue ======================================
    {
        float* red = (float*)sraw;
        float s = key2f(g_aminU[blk * 1024 + t]) + key2f(g_aminU[blk * 1024 + 512 + t]);
        if (t < 16) s += key2f(g_bminU[blk * 16 + t]);
        red[t] = s;
        __syncthreads();
        #pragma unroll
        for (int st = 256; st > 0; st >>= 1) {
            if (t < st) red[t] += red[t + st];
            __syncthreads();
        }
        if (t == 0) {
            atomicAdd(&g_lossA, red[0]);
            __threadfence();
            unsigned v = atomicAdd(&g_done, 1u);
            if (v == 127u) {   // last block: publish + reset for next replay
                out[0] = 2.0f * (*(volatile float*)&g_lossA);
                g_barcnt = 0u;
                g_done   = 0u;
                __threadfence();
            }
        }
    }
}

// ---------------- launch ----------------------------------------------------
extern "C" void kernel_launch(void* const* d_in, const int* in_sizes, int n_in,
                              void* d_out, int out_size) {
    const float* x    = (const float*)d_in[0];
    const float* grid = (const float*)d_in[1];
    const float* We1  = (const float*)d_in[2];
    const float* be1  = (const float*)d_in[3];
    const float* We2  = (const float*)d_in[4];
    const float* be2  = (const float*)d_in[5];
    const float* We3  = (const float*)d_in[6];
    const float* be3  = (const float*)d_in[7];
    const float* Wd1  = (const float*)d_in[8];
    const float* bd1  = (const float*)d_in[9];
    const float* Wd2  = (const float*)d_in[10];
    const float* bd2  = (const float*)d_in[11];
    const float* Wd3  = (const float*)d_in[12];
    const float* bd3  = (const float*)d_in[13];
    float* out = (float*)d_out;

    k_mega<<<128, 512>>>(x, grid, We1, be1, We2, be2, We3, be3,
                         Wd1, bd1, Wd2, bd2, Wd3, bd3, out);
}

// round 8
// speedup vs baseline: 2.5659x; 1.1408x over previous
#include <cuda_runtime.h>

typedef unsigned long long u64;

// ---------------- scratch (device globals) ---------------------------------
__device__ float g_p1[8 * 2 * 512];       // enc1 k-partials
__device__ float g_z[2 * 64];
__device__ float g_d2[2 * 64 * 512];
__device__ float g_Y[2 * 65536 * 3];
__device__ float g_lossA;
__device__ unsigned g_aminU[2 * 65536];
__device__ unsigned g_bminU[2 * 1024];
__device__ unsigned g_barcnt;
__device__ unsigned g_done;

// ---------------- f32x2 helpers -------------------------------------------
__device__ __forceinline__ u64 pk2(float a, float b) {
    u64 r; asm("mov.b64 %0, {%1,%2};" : "=l"(r) : "f"(a), "f"(b)); return r;
}
__device__ __forceinline__ float2 upk(u64 v) {
    float2 r; asm("mov.b64 {%0,%1}, %2;" : "=f"(r.x), "=f"(r.y) : "l"(v)); return r;
}
__device__ __forceinline__ u64 fma2_(u64 a, u64 b, u64 c) {
    u64 d; asm("fma.rn.f32x2 %0, %1, %2, %3;" : "=l"(d) : "l"(a), "l"(b), "l"(c)); return d;
}
__device__ __forceinline__ u64 add2_(u64 a, u64 b) {
    u64 d; asm("add.rn.f32x2 %0, %1, %2;" : "=l"(d) : "l"(a), "l"(b)); return d;
}
__device__ __forceinline__ unsigned f2key(float f) {
    unsigned b = __float_as_uint(f);
    return b ^ ((unsigned)((int)b >> 31) | 0x80000000u);
}
__device__ __forceinline__ float key2f(unsigned k) {
    unsigned b = (k & 0x80000000u) ? (k ^ 0x80000000u) : ~k;
    return __uint_as_float(b);
}
__device__ __forceinline__ void pfL2(const void* p) {
    asm volatile("prefetch.global.L2 [%0];" :: "l"(p));
}

// ---------------- grid-wide spin barrier -----------------------------------
__device__ __forceinline__ void gbar(unsigned target) {
    __threadfence();
    __syncthreads();
    if (threadIdx.x == 0) {
        atomicAdd(&g_barcnt, 1u);
        while (*(volatile unsigned*)&g_barcnt < target) __nanosleep(32);
    }
    __syncthreads();
}

// ---------------- the megakernel -------------------------------------------
__global__ void __launch_bounds__(512, 1) k_mega(
    const float* __restrict__ x,   const float* __restrict__ grid_pts,
    const float* __restrict__ We1, const float* __restrict__ be1,
    const float* __restrict__ We2, const float* __restrict__ be2,
    const float* __restrict__ We3, const float* __restrict__ be3,
    const float* __restrict__ Wd1, const float* __restrict__ bd1,
    const float* __restrict__ Wd2, const float* __restrict__ bd2,
    const float* __restrict__ Wd3, const float* __restrict__ bd3,
    float* __restrict__ out)
{
    __shared__ __align__(16) unsigned char sraw[20608];
    const int t    = threadIdx.x;
    const int blk  = blockIdx.x;
    const int lane = t & 31;
    const int wid  = t >> 5;

    // ===== P0: enc1 partials (128 blocks) + init + L2 weight prefetch ======
    {
        float* xs  = (float*)sraw;          // [2][384]
        float* red = xs + 768;              // [2][512]
        int bx = blk >> 3, by = blk & 7;
        int col = bx * 32 + lane;
        for (int i = t; i < 768; i += 512) {
            int bb = (i >= 384), kk = i - bb * 384;
            xs[bb * 384 + kk] = x[bb * 3072 + by * 384 + kk];
        }
        // ---- warm L2 with every later-phase weight (one 128B line/thread) --
        {
            int gtid = blk * 512 + t;       // 0..65535
            if (gtid < 49152) {             // Wd3: 512*3072 floats = 49152 lines
                pfL2((const char*)Wd3 + (size_t)gtid * 128);
            } else {
                int r = gtid - 49152;       // 0..16383
                if (r < 2048)      pfL2((const char*)Wd2 + (size_t)r * 128);          // 128*512
                else if (r < 4096) pfL2((const char*)We2 + (size_t)(r - 2048) * 128); // 512*128
                else if (r < 4364) pfL2((const char*)Wd1 + (size_t)(r - 4096) * 128); // 67*128
                else if (r < 4620) pfL2((const char*)We3 + (size_t)(r - 4364) * 128); // 128*64
            }
        }
        g_aminU[blk * 1024 + t]       = 0xFFFFFFFFu;
        g_aminU[blk * 1024 + 512 + t] = 0xFFFFFFFFu;
        if (t < 16) g_bminU[blk * 16 + t] = 0xFFFFFFFFu;
        if (blk == 0 && t == 0) g_lossA = 0.0f;
        __syncthreads();
        float a0 = 0.0f, a1 = 0.0f;
        int k0 = by * 384 + wid * 24, kl0 = wid * 24;
        float w[24];
        #pragma unroll
        for (int j = 0; j < 24; ++j) w[j] = We1[(k0 + j) * 512 + col];
        #pragma unroll
        for (int j = 0; j < 24; ++j) {
            a0 = fmaf(xs[kl0 + j],       w[j], a0);
            a1 = fmaf(xs[384 + kl0 + j], w[j], a1);
        }
        red[t]       = a0;
        red[512 + t] = a1;
        __syncthreads();
        if (t < 64) {
            int bb = t >> 5, ll = t & 31;
            float s = 0.0f;
            #pragma unroll
            for (int r = 0; r < 16; ++r) s += red[bb * 512 + r * 32 + ll];
            g_p1[(by * 2 + bb) * 512 + bx * 32 + ll] = s;
        }
    }
    gbar(128);

    // ===== P1: encoder layers 1-combine, 2, 3 (2 blocks, 512 thr) ==========
    if (blk < 2) {
        float* h1s = (float*)sraw;          // [512]
        float* hp  = h1s + 512;             // [4][128]
        float* h2s = hp + 512;              // [128]
        float* zp  = h2s + 128;             // [8][64]
        int b = blk;
        {
            float s = be1[t];
            #pragma unroll
            for (int sl = 0; sl < 8; ++sl) s += g_p1[(sl * 2 + b) * 512 + t];
            h1s[t] = fmaxf(s, 0.0f);
        }
        __syncthreads();
        {
            int ks = t >> 7, col = t & 127;
            int k0 = ks * 128;
            float acc = 0.0f;
            #pragma unroll 1
            for (int c = 0; c < 8; ++c) {
                float w[16];
                #pragma unroll
                for (int j = 0; j < 16; ++j) w[j] = We2[(k0 + c * 16 + j) * 128 + col];
                #pragma unroll
                for (int j = 0; j < 16; ++j) acc = fmaf(h1s[k0 + c * 16 + j], w[j], acc);
            }
            hp[ks * 128 + col] = acc;
        }
        __syncthreads();
        if (t < 128)
            h2s[t] = fmaxf(hp[t] + hp[128 + t] + hp[256 + t] + hp[384 + t] + be2[t], 0.0f);
        __syncthreads();
        {
            int ks = t >> 6, col = t & 63;
            float w[16];
            #pragma unroll
            for (int j = 0; j < 16; ++j) w[j] = We3[(ks * 16 + j) * 64 + col];
            float acc = 0.0f;
            #pragma unroll
            for (int j = 0; j < 16; ++j) acc = fmaf(h2s[ks * 16 + j], w[j], acc);
            zp[ks * 64 + col] = acc;
        }
        __syncthreads();
        if (t < 64) {
            float s = be3[t];
            #pragma unroll
            for (int sl = 0; sl < 8; ++sl) s += zp[sl * 64 + t];
            g_z[b * 64 + t] = fmaxf(s, 0.0f);
        }
    }
    gbar(256);

    // ===== P2: dec1 + dec2 fused (64 blocks, 2 rows each) ===================
    if (blk < 64) {
        u64*   d1p = (u64*)sraw;            // [128]
        float* zi  = (float*)(sraw + 1024); // [2][67]
        float* d1s = (float*)(sraw + 1664); // [2][128]
        int r0 = blk * 2;
        int b  = r0 >> 6;
        if (t < 134) {
            int rw = (t >= 67), i = t - rw * 67;
            int g = (r0 + rw) & 63;
            zi[rw * 67 + i] = (i < 64) ? g_z[b * 64 + i] : grid_pts[g * 3 + (i - 64)];
        }
        __syncthreads();
        if (t < 256) {
            int rw = t >> 7, col = t & 127;
            float acc = bd1[col];
            #pragma unroll 1
            for (int c = 0; c < 4; ++c) {
                float w[16];
                #pragma unroll
                for (int j = 0; j < 16; ++j) w[j] = Wd1[(c * 16 + j) * 128 + col];
                #pragma unroll
                for (int j = 0; j < 16; ++j) acc = fmaf(zi[rw * 67 + c * 16 + j], w[j], acc);
            }
            {
                float w0 = Wd1[64 * 128 + col], w1 = Wd1[65 * 128 + col], w2 = Wd1[66 * 128 + col];
                acc = fmaf(zi[rw * 67 + 64], w0, acc);
                acc = fmaf(zi[rw * 67 + 65], w1, acc);
                acc = fmaf(zi[rw * 67 + 66], w2, acc);
            }
            d1s[rw * 128 + col] = fmaxf(acc, 0.0f);
        }
        __syncthreads();
        if (t < 128) d1p[t] = pk2(d1s[t], d1s[128 + t]);
        __syncthreads();
        u64 acc = 0ull;
        #pragma unroll 1
        for (int c = 0; c < 8; ++c) {
            float w[16];
            #pragma unroll
            for (int j = 0; j < 16; ++j) w[j] = Wd2[(c * 16 + j) * 512 + t];
            #pragma unroll
            for (int j = 0; j < 16; ++j) acc = fma2_(d1p[c * 16 + j], pk2(w[j], w[j]), acc);
        }
        float2 v = upk(acc);
        float bb = bd2[t];
        g_d2[(r0 + 0) * 512 + t] = fmaxf(v.x + bb, 0.0f);
        g_d2[(r0 + 1) * 512 + t] = fmaxf(v.y + bb, 0.0f);
    }
    gbar(384);

    // ===== P3: dec3 [128,512]x[512,3072] + tanh (128 blocks) ================
    {
        float* As = (float*)sraw;           // [512][10] padded
        int rg = blk >> 3, cg = blk & 7;    // 16 rowgroups(8) x 8 colgroups(384)
        int r0 = rg * 8;
        for (int idx = t; idx < 4096; idx += 512) {
            int r = idx & 7, k = idx >> 3;
            As[k * 10 + r] = g_d2[(r0 + r) * 512 + k];
        }
        __syncthreads();
        if (t < 384) {
            int col = cg * 384 + t;
            u64 acc0 = 0ull, acc1 = 0ull, acc2 = 0ull, acc3 = 0ull;
            #pragma unroll 1
            for (int c = 0; c < 32; ++c) {
                float w[16];
                #pragma unroll
                for (int j = 0; j < 16; ++j) w[j] = Wd3[(c * 16 + j) * 3072 + col];
                #pragma unroll
                for (int j = 0; j < 16; ++j) {
                    u64 w2 = pk2(w[j], w[j]);
                    const ulonglong2* ap = (const ulonglong2*)&As[(c * 16 + j) * 10];
                    ulonglong2 q0 = ap[0], q1 = ap[1];
                    acc0 = fma2_(q0.x, w2, acc0);
                    acc1 = fma2_(q0.y, w2, acc1);
                    acc2 = fma2_(q1.x, w2, acc2);
                    acc3 = fma2_(q1.y, w2, acc3);
                }
            }
            float bb = bd3[col];
            float2 v0 = upk(acc0), v1 = upk(acc1), v2 = upk(acc2), v3 = upk(acc3);
            g_Y[(r0 + 0) * 3072 + col] = tanhf(v0.x + bb);
            g_Y[(r0 + 1) * 3072 + col] = tanhf(v0.y + bb);
            g_Y[(r0 + 2) * 3072 + col] = tanhf(v1.x + bb);
            g_Y[(r0 + 3) * 3072 + col] = tanhf(v1.y + bb);
            g_Y[(r0 + 4) * 3072 + col] = tanhf(v2.x + bb);
            g_Y[(r0 + 5) * 3072 + col] = tanhf(v2.y + bb);
            g_Y[(r0 + 6) * 3072 + col] = tanhf(v3.x + bb);
            g_Y[(r0 + 7) * 3072 + col] = tanhf(v3.y + bb);
        }
    }
    gbar(512);

    // ===== P4: symmetric chamfer, systolic ring (16 Y/lane, 128 S/block) ====
    {
        unsigned* sbmin = (unsigned*)sraw;   // [128]
        int b = blk >> 6, inner = blk & 63;
        int yt = inner >> 3, ms = inner & 7;
        if (t < 128) sbmin[t] = 0xFFFFFFFFu;

        int nbase = b * 65536 + yt * 8192 + wid * 512;
        u64 px[8], py[8], pz[8], ph[8];
        #pragma unroll
        for (int p = 0; p < 8; ++p) {
            int n0 = nbase + (2 * p) * 32 + lane;
            int n1 = nbase + (2 * p + 1) * 32 + lane;
            float a0 = g_Y[n0 * 3 + 0], a1 = g_Y[n0 * 3 + 1], a2 = g_Y[n0 * 3 + 2];
            float c0 = g_Y[n1 * 3 + 0], c1 = g_Y[n1 * 3 + 1], c2 = g_Y[n1 * 3 + 2];
            px[p] = pk2(a0, c0);
            py[p] = pk2(a1, c1);
            pz[p] = pk2(a2, c2);
            ph[p] = pk2(0.5f * (a0 * a0 + a1 * a1 + a2 * a2),
                        0.5f * (c0 * c0 + c1 * c1 + c2 * c2));
        }
        float amin[16];
        #pragma unroll
        for (int j = 0; j < 16; ++j) amin[j] = 3.4e38f;
        __syncthreads();

        int m0 = b * 1024 + ms * 128;
        for (int g = 0; g < 4; ++g) {
            int m = m0 + g * 32 + lane;
            float sx = x[m * 3 + 0], sy = x[m * 3 + 1], sz = x[m * 3 + 2];
            float nx = -sx, ny = -sy, nz = -sz;
            float hs = 0.5f * (sx * sx + sy * sy + sz * sz);
            float bacc = 3.4e38f;
            #pragma unroll 4
            for (int step = 0; step < 32; ++step) {
                u64 nx2 = pk2(nx, nx), ny2 = pk2(ny, ny);
                u64 nz2 = pk2(nz, nz), hs2 = pk2(hs, hs);
                float tm[8];
                #pragma unroll
                for (int p = 0; p < 8; ++p) {
                    u64 v2 = fma2_(px[p], nx2,
                             fma2_(py[p], ny2,
                             fma2_(pz[p], nz2, add2_(ph[p], hs2))));
                    float2 va = upk(v2);
                    amin[2 * p + 0] = fminf(amin[2 * p + 0], va.x);
                    amin[2 * p + 1] = fminf(amin[2 * p + 1], va.y);
                    tm[p] = fminf(va.x, va.y);
                }
                float t0 = fminf(fminf(tm[0], tm[1]), fminf(tm[2], tm[3]));
                float t1 = fminf(fminf(tm[4], tm[5]), fminf(tm[6], tm[7]));
                bacc = fminf(bacc, fminf(t0, t1));
                int src = (lane + 1) & 31;
                nx   = __shfl_sync(0xffffffffu, nx,   src);
                ny   = __shfl_sync(0xffffffffu, ny,   src);
                nz   = __shfl_sync(0xffffffffu, nz,   src);
                hs   = __shfl_sync(0xffffffffu, hs,   src);
                bacc = __shfl_sync(0xffffffffu, bacc, src);
            }
            atomicMin(&sbmin[g * 32 + lane], f2key(bacc));
        }
        __syncthreads();
        if (t < 128) atomicMin(&g_bminU[m0 + t], sbmin[t]);
        #pragma unroll
        for (int p = 0; p < 8; ++p) {
            atomicMin(&g_aminU[nbase + (2 * p) * 32 + lane],     f2key(amin[2 * p]));
            atomicMin(&g_aminU[nbase + (2 * p + 1) * 32 + lane], f2key(amin[2 * p + 1]));
        }
    }
    gbar(640);

    // ===== P5: final reduce + epilogue ======================================
    {
        float* red = (float*)sraw;
        float s = key2f(g_aminU[blk * 1024 + t]) + key2f(g_aminU[blk * 1024 + 512 + t]);
        if (t < 16) s += key2f(g_bminU[blk * 16 + t]);
        red[t] = s;
        __syncthreads();
        #pragma unroll
        for (int st = 256; st > 0; st >>= 1) {
            if (t < st) red[t] += red[t + st];
            __syncthreads();
        }
        if (t == 0) {
            atomicAdd(&g_lossA, red[0]);
            __threadfence();
            unsigned v = atomicAdd(&g_done, 1u);
            if (v == 127u) {   // last block: publish + reset for next replay
                out[0] = 2.0f * (*(volatile float*)&g_lossA);
                g_barcnt = 0u;
                g_done   = 0u;
                __threadfence();
            }
        }
    }
}

// ---------------- launch ----------------------------------------------------
extern "C" void kernel_launch(void* const* d_in, const int* in_sizes, int n_in,
                              void* d_out, int out_size) {
    const float* x    = (const float*)d_in[0];
    const float* grid = (const float*)d_in[1];
    const float* We1  = (const float*)d_in[2];
    const float* be1  = (const float*)d_in[3];
    const float* We2  = (const float*)d_in[4];
    const float* be2  = (const float*)d_in[5];
    const float* We3  = (const float*)d_in[6];
    const float* be3  = (const float*)d_in[7];
    const float* Wd1  = (const float*)d_in[8];
    const float* bd1  = (const float*)d_in[9];
    const float* Wd2  = (const float*)d_in[10];
    const float* bd2  = (const float*)d_in[11];
    const float* Wd3  = (const float*)d_in[12];
    const float* bd3  = (const float*)d_in[13];
    float* out = (float*)d_out;

    k_mega<<<128, 512>>>(x, grid, We1, be1, We2, be2, We3, be3,
                         Wd1, bd1, Wd2, bd2, Wd3, bd3, out);
}